// round 4
// baseline (speedup 1.0000x reference)
#include <cuda_runtime.h>
#include <cuda_bf16.h>

#define NTOK   55392      // 96 * 577 tokens
#define BHN    96
#define QT     577
#define MASK_ELEMS (96 * 577 * 577)   // 31,961,184
#define NCHUNK (MASK_ELEMS / 16)      // 1,997,574 (exact)
#define SIGMA_ELEMS (NTOK * 4)

// Scratch: per-token layer-2 partials (2 half-group partials x (p0,p1,p2,pad))
__device__ float4 g_part[NTOK * 2];
// Per-token inverse-covariance coefficients (inv00, inv01, inv11, pad)
__device__ float4 g_coef[NTOK];
// Fallback Sigma target if out buffer doesn't include Sigma
__device__ float  g_sigma_fallback[SIGMA_ELEMS];

// ---------------------------------------------------------------------------
// Kernel A: MLP layer1 + GELU + layer2 partials. 256 threads = 4 groups of 64.
// Block handles 32 tokens (8 per group). ONE __syncthreads per block.
// 4 independent accumulators break the dependent-FMA chain (ILP=4).
// ---------------------------------------------------------------------------
__global__ __launch_bounds__(256)
void mgk_mlp_partial(const float* __restrict__ q,
                     const float* __restrict__ W1, const float* __restrict__ b1,
                     const float* __restrict__ W2)
{
    __shared__ float4 qs4[32][16];       // 32 tokens x 64 floats = 8KB

    const int tid  = threadIdx.x;
    const int g    = tid >> 6;           // group 0..3
    const int j    = tid & 63;           // hidden unit
    const int half = (tid >> 5) & 1;     // warp within group
    const int lane = tid & 31;

    // Register-resident W1 column j (coalesced across j)
    float w[64];
#pragma unroll
    for (int k = 0; k < 64; k++) w[k] = W1[k * 64 + j];
    const float bias = b1[j];
    const float w2a = W2[j * 3 + 0];
    const float w2b = W2[j * 3 + 1];
    const float w2c = W2[j * 3 + 2];

    // Stage 32 tokens' q vectors: 2048 floats = 2 float4 per thread
    const int tok0 = blockIdx.x * 32;          // NTOK = 32*1731 exactly
    {
        const float4* src = (const float4*)(q + (size_t)tok0 * 64);
        float4* dst = &qs4[0][0];
        dst[tid]       = src[tid];
        dst[tid + 256] = src[tid + 256];
    }
    __syncthreads();

    for (int i = 0; i < 8; i++) {              // 8 tokens per group, no syncs
        const int tl  = g * 8 + i;
        const int tok = tok0 + tl;

        // 4 independent partial sums over interleaved k-chunks
        float h0 = bias, h1 = 0.0f, h2 = 0.0f, h3 = 0.0f;
#pragma unroll
        for (int kk = 0; kk < 4; kk++) {
            float4 v0 = qs4[tl][4 * kk + 0];
            float4 v1 = qs4[tl][4 * kk + 1];
            float4 v2 = qs4[tl][4 * kk + 2];
            float4 v3 = qs4[tl][4 * kk + 3];
            h0 = fmaf(v0.x, w[16 * kk + 0],  h0);
            h0 = fmaf(v0.y, w[16 * kk + 1],  h0);
            h0 = fmaf(v0.z, w[16 * kk + 2],  h0);
            h0 = fmaf(v0.w, w[16 * kk + 3],  h0);
            h1 = fmaf(v1.x, w[16 * kk + 4],  h1);
            h1 = fmaf(v1.y, w[16 * kk + 5],  h1);
            h1 = fmaf(v1.z, w[16 * kk + 6],  h1);
            h1 = fmaf(v1.w, w[16 * kk + 7],  h1);
            h2 = fmaf(v2.x, w[16 * kk + 8],  h2);
            h2 = fmaf(v2.y, w[16 * kk + 9],  h2);
            h2 = fmaf(v2.z, w[16 * kk + 10], h2);
            h2 = fmaf(v2.w, w[16 * kk + 11], h2);
            h3 = fmaf(v3.x, w[16 * kk + 12], h3);
            h3 = fmaf(v3.y, w[16 * kk + 13], h3);
            h3 = fmaf(v3.z, w[16 * kk + 14], h3);
            h3 = fmaf(v3.w, w[16 * kk + 15], h3);
        }
        const float h = (h0 + h1) + (h2 + h3);

        // Exact GELU (erf-based, matches approximate=False)
        const float ge = 0.5f * h * (1.0f + erff(h * 0.70710678118654752f));

        float p0 = ge * w2a, p1 = ge * w2b, p2 = ge * w2c;
#pragma unroll
        for (int off = 16; off > 0; off >>= 1) {
            p0 += __shfl_xor_sync(0xffffffffu, p0, off);
            p1 += __shfl_xor_sync(0xffffffffu, p1, off);
            p2 += __shfl_xor_sync(0xffffffffu, p2, off);
        }
        if (lane == 0)
            g_part[tok * 2 + half] = make_float4(p0, p1, p2, 0.0f);
    }
}

// ---------------------------------------------------------------------------
// Kernel B: finalize per token — fully parallel exp/tanh/inverse.
// ---------------------------------------------------------------------------
__global__ __launch_bounds__(256)
void mgk_mlp_final(const float* __restrict__ b2, float* __restrict__ sigma_out)
{
    const int tok = blockIdx.x * 256 + threadIdx.x;
    if (tok >= NTOK) return;

    const float4 pa = g_part[tok * 2 + 0];
    const float4 pb = g_part[tok * 2 + 1];
    const float s0 = pa.x + pb.x + b2[0];
    const float s1 = pa.y + pb.y + b2[1];
    const float s2 = pa.z + pb.z + b2[2];

    const float sy  = expf(s0) + 1.0f;
    const float sx  = expf(s1) + 1.0f;
    const float rho = tanhf(s2) * 0.99f;
    const float cov = sy * sx * rho;

    ((float4*)sigma_out)[tok] = make_float4(sy * sy, cov, cov, sx * sx);

    const float om  = 1.0f - rho * rho;
    const float i00 = 1.0f / (sy * sy * om);
    const float i11 = 1.0f / (sx * sx * om);
    const float i01 = -rho / (sy * sx * om);
    g_coef[tok] = make_float4(i00, i01, i11, 0.0f);
}

// ---------------------------------------------------------------------------
// Kernel C: elementwise mask. One thread = 16 CONTIGUOUS elements:
// 4 consecutive LDG.128 in flight + 4 STG.128, index math amortized.
// dists analytic (no loads): dy=row(q)-row(k), dx=col(q)-col(k), 0 for CLS.
// max_k kernel == 1 exactly (PD form, self-distance 0) => no row reduction.
// T==1 fast path: mask = p*u / (p*u + (1-p)(1-u)), p = exp(-quad/2).
// ---------------------------------------------------------------------------
__device__ __forceinline__ float mask_one(float dy, float dx,
                                          float a00, float a01x2, float a11,
                                          float uu, bool isT1, float invT)
{
    float quad = a00 * dy * dy;
    quad = fmaf(a01x2 * dy, dx, quad);
    quad = fmaf(a11 * dx, dx, quad);
    quad = fmaxf(quad, 0.0f);                        // replicate min(probs,1)
    const float t2 = -0.72134752044448170f * quad;   // -0.5*log2(e)*quad
    const float p  = exp2f(t2);
    if (isT1) {
        const float a = p * uu;
        const float b = (1.0f - p) * (1.0f - uu);
        return __fdividef(a, a + b);
    } else {
        const float x2 = t2 + __log2f(uu) - __log2f((1.0f - p) * (1.0f - uu));
        return __fdividef(1.0f, 1.0f + exp2f(-x2 * invT));
    }
}

// exact floor(pk/24) for 0 <= pk < 576
__device__ __forceinline__ int div24(int pk) { return (pk * 2731) >> 16; }

__global__ __launch_bounds__(256)
void mgk_mask_kernel(const float4* __restrict__ u4,
                     const float* __restrict__ temp,
                     float4* __restrict__ out4)
{
    const unsigned chunk = blockIdx.x * 256u + threadIdx.x;
    if (chunk >= NCHUNK) return;

    const float T    = temp[0];
    const bool  isT1 = (T == 1.0f);
    const float invT = 1.0f / T;

    // 64 bytes of u in flight per thread (4 consecutive LDG.128)
    float4 uu0 = u4[chunk * 4 + 0];
    float4 uu1 = u4[chunk * 4 + 1];
    float4 uu2 = u4[chunk * 4 + 2];
    float4 uu3 = u4[chunk * 4 + 3];
    const float ue[16] = {uu0.x, uu0.y, uu0.z, uu0.w,
                          uu1.x, uu1.y, uu1.z, uu1.w,
                          uu2.x, uu2.y, uu2.z, uu2.w,
                          uu3.x, uu3.y, uu3.z, uu3.w};

    const unsigned idx0 = chunk * 16u;
    const unsigned row  = idx0 / 577u;          // = bh*577 + q
    const unsigned k0   = idx0 - row * 577u;

    float me[16];

    if (k0 <= 561u) {                           // all 16 in the same row
        const float4 c = g_coef[row];
        const float a00 = c.x, a01x2 = 2.0f * c.y, a11 = c.z;
        const unsigned qrow = row % 577u;
        const bool qcls = (qrow == 0u);

        if (qcls) {                             // whole row: dy=dx=0 -> p=1
#pragma unroll
            for (int jj = 0; jj < 16; jj++)
                me[jj] = isT1 ? 1.0f
                              : mask_one(0.f, 0.f, a00, a01x2, a11,
                                         ue[jj], isT1, invT);
        } else {
            const int pq = (int)qrow - 1;
            const int qr = div24(pq), qc = pq - 24 * qr;
            // (r,cc) for patch index of current k (valid when k>=1),
            // advanced incrementally — no per-element division.
            int kk = (int)k0;
            int pk = (kk == 0) ? 0 : kk - 1;
            int r  = div24(pk), cc = pk - 24 * r;
#pragma unroll
            for (int jj = 0; jj < 16; jj++) {
                float dy, dx;
                if (kk == 0) { dy = 0.0f; dx = 0.0f; }
                else {
                    dy = (float)(qr - r);
                    dx = (float)(qc - cc);
                    cc++; if (cc == 24) { cc = 0; r++; }   // advance to next k
                }
                me[jj] = mask_one(dy, dx, a00, a01x2, a11, ue[jj], isT1, invT);
                kk++;
            }
        }
    } else {                                    // row-boundary straddle (~2.8%)
#pragma unroll
        for (int jj = 0; jj < 16; jj++) {
            const unsigned idx = idx0 + jj;
            const unsigned rr  = idx / 577u;
            const int      kk  = (int)(idx - rr * 577u);
            const unsigned qq  = rr % 577u;
            const float4 c = g_coef[rr];
            float dy = 0.0f, dx = 0.0f;
            if (qq != 0u && kk != 0) {
                const int pq = (int)qq - 1;
                const int qr2 = div24(pq), qc2 = pq - 24 * qr2;
                const int pk = kk - 1;
                const int r  = div24(pk), cc = pk - 24 * r;
                dy = (float)(qr2 - r);
                dx = (float)(qc2 - cc);
            }
            me[jj] = mask_one(dy, dx, c.x, 2.0f * c.y, c.z, ue[jj], isT1, invT);
        }
    }

    out4[chunk * 4 + 0] = make_float4(me[0],  me[1],  me[2],  me[3]);
    out4[chunk * 4 + 1] = make_float4(me[4],  me[5],  me[6],  me[7]);
    out4[chunk * 4 + 2] = make_float4(me[8],  me[9],  me[10], me[11]);
    out4[chunk * 4 + 3] = make_float4(me[12], me[13], me[14], me[15]);
}

// ---------------------------------------------------------------------------
extern "C" void kernel_launch(void* const* d_in, const int* in_sizes, int n_in,
                              void* d_out, int out_size)
{
    const float* query = (const float*)d_in[0];
    const float* W1    = (const float*)d_in[1];
    const float* b1    = (const float*)d_in[2];
    const float* W2    = (const float*)d_in[3];
    const float* b2    = (const float*)d_in[4];
    // d_in[5] = dists (computed analytically in-kernel)
    const float* u     = (const float*)d_in[6];
    const float* temp  = (const float*)d_in[7];

    float* mask = (float*)d_out;

    float* sigma;
    if (out_size >= MASK_ELEMS + SIGMA_ELEMS) {
        sigma = (float*)d_out + MASK_ELEMS;
    } else {
        cudaGetSymbolAddress((void**)&sigma, g_sigma_fallback);
    }

    mgk_mlp_partial<<<NTOK / 32, 256>>>(query, W1, b1, W2);   // 1731 blocks
    mgk_mlp_final<<<(NTOK + 255) / 256, 256>>>(b2, sigma);    // 217 blocks
    mgk_mask_kernel<<<(NCHUNK + 255) / 256, 256>>>((const float4*)u, temp,
                                                   (float4*)mask);
}

// round 6
// speedup vs baseline: 1.0739x; 1.0739x over previous
#include <cuda_runtime.h>
#include <cuda_bf16.h>

#define NTOK   55392              // 96 * 577 tokens == rows
#define QT     577
#define MASK_ELEMS (96 * 577 * 577)
#define SIGMA_ELEMS (NTOK * 4)
#define RPB    16                 // rows per block (NTOK = 16 * 3462 exactly)

// Fallback Sigma target if out buffer doesn't include Sigma
__device__ float g_sigma_fallback[SIGMA_ELEMS];

// ---------------------------------------------------------------------------
// Fully fused kernel. One 64-thread block processes 16 consecutive rows
// (= tokens). Per row:
//   1. MLP: thread j owns hidden unit j, W1 column register-resident and
//      REUSED across all 16 rows. q staged in SMEM (broadcast LDS.128).
//   2. Butterfly-reduce layer-2, thread 0 computes Sigma + inverse coefs.
//   3. Mask: 577 elements, lane-coalesced (k = tid + 64*i), u loads batched
//      10-deep in flight, dists analytic (no loads), incremental (r,cc) walk.
// max_k kernel == 1 exactly (PD form, zero self/CLS distance) => no row
// reduction. T==1 fast path: mask = p*u / (p*u + (1-p)(1-u)), p=exp(-quad/2).
// ---------------------------------------------------------------------------
__global__ __launch_bounds__(64)
void mgk_fused(const float* __restrict__ q,
               const float* __restrict__ W1, const float* __restrict__ b1,
               const float* __restrict__ W2, const float* __restrict__ b2,
               const float* __restrict__ u,  const float* __restrict__ temp,
               float* __restrict__ mask, float* __restrict__ sigma)
{
    __shared__ float4 qs4[16];       // current token's 64 q floats
    __shared__ float  wpart[2][3];   // per-warp layer-2 partials
    __shared__ float  scoef[3];      // i00, i01, i11

    const int tid  = threadIdx.x;
    const int lane = tid & 31;
    const int wid  = tid >> 5;

    // Register-resident W1 column j = tid (coalesced load, reused 16 rows)
    float w[64];
#pragma unroll
    for (int k = 0; k < 64; k++) w[k] = W1[k * 64 + tid];
    const float bias = b1[tid];
    const float w2a = W2[tid * 3 + 0];
    const float w2b = W2[tid * 3 + 1];
    const float w2c = W2[tid * 3 + 2];
    const float b20 = b2[0], b21 = b2[1], b22 = b2[2];
    const float T    = temp[0];
    const bool  isT1 = (T == 1.0f);
    const float invT = 1.0f / T;

    const int tok0 = blockIdx.x * RPB;

    for (int rr = 0; rr < RPB; rr++) {
        const int tok = tok0 + rr;

        // ---- stage q (64 floats, coalesced) ----
        ((float*)qs4)[tid] = q[(size_t)tok * 64 + tid];
        __syncthreads();                                   // sync #1

        // ---- layer 1: h_j = b1[j] + q . W1[:, j], 4 independent accums ----
        float h0 = bias, h1 = 0.0f, h2 = 0.0f, h3 = 0.0f;
#pragma unroll
        for (int kk = 0; kk < 4; kk++) {
            float4 v0 = qs4[4 * kk + 0];
            float4 v1 = qs4[4 * kk + 1];
            float4 v2 = qs4[4 * kk + 2];
            float4 v3 = qs4[4 * kk + 3];
            h0 = fmaf(v0.x, w[16 * kk + 0],  h0);
            h0 = fmaf(v0.y, w[16 * kk + 1],  h0);
            h0 = fmaf(v0.z, w[16 * kk + 2],  h0);
            h0 = fmaf(v0.w, w[16 * kk + 3],  h0);
            h1 = fmaf(v1.x, w[16 * kk + 4],  h1);
            h1 = fmaf(v1.y, w[16 * kk + 5],  h1);
            h1 = fmaf(v1.z, w[16 * kk + 6],  h1);
            h1 = fmaf(v1.w, w[16 * kk + 7],  h1);
            h2 = fmaf(v2.x, w[16 * kk + 8],  h2);
            h2 = fmaf(v2.y, w[16 * kk + 9],  h2);
            h2 = fmaf(v2.z, w[16 * kk + 10], h2);
            h2 = fmaf(v2.w, w[16 * kk + 11], h2);
            h3 = fmaf(v3.x, w[16 * kk + 12], h3);
            h3 = fmaf(v3.y, w[16 * kk + 13], h3);
            h3 = fmaf(v3.z, w[16 * kk + 14], h3);
            h3 = fmaf(v3.w, w[16 * kk + 15], h3);
        }
        const float h  = (h0 + h1) + (h2 + h3);
        // Exact GELU (erf-based, matches approximate=False)
        const float ge = 0.5f * h * (1.0f + erff(h * 0.70710678118654752f));

        // ---- layer 2 partials + butterfly reduce ----
        float p0 = ge * w2a, p1 = ge * w2b, p2 = ge * w2c;
#pragma unroll
        for (int off = 16; off > 0; off >>= 1) {
            p0 += __shfl_xor_sync(0xffffffffu, p0, off);
            p1 += __shfl_xor_sync(0xffffffffu, p1, off);
            p2 += __shfl_xor_sync(0xffffffffu, p2, off);
        }
        if (lane == 0) {
            wpart[wid][0] = p0; wpart[wid][1] = p1; wpart[wid][2] = p2;
        }
        __syncthreads();                                   // sync #2

        if (tid == 0) {
            const float s0 = wpart[0][0] + wpart[1][0] + b20;
            const float s1 = wpart[0][1] + wpart[1][1] + b21;
            const float s2 = wpart[0][2] + wpart[1][2] + b22;

            const float sy  = expf(s0) + 1.0f;
            const float sx  = expf(s1) + 1.0f;
            const float rho = tanhf(s2) * 0.99f;
            const float cov = sy * sx * rho;

            ((float4*)sigma)[tok] = make_float4(sy * sy, cov, cov, sx * sx);

            const float om = 1.0f - rho * rho;
            scoef[0] = 1.0f / (sy * sy * om);
            scoef[1] = -rho / (sy * sx * om);
            scoef[2] = 1.0f / (sx * sx * om);
        }
        __syncthreads();                                   // sync #3

        const float a00   = scoef[0];
        const float a01x2 = 2.0f * scoef[1];
        const float a11   = scoef[2];

        const int    qrow = tok % QT;
        const float* urow = u    + (size_t)tok * QT;
        float*       mrow = mask + (size_t)tok * QT;

        if (qrow == 0) {
            // CLS query row: dy=dx=0 everywhere -> probs=1 -> logits=+inf
            // -> mask = 1 for ANY temperature.
            for (int k = tid; k < QT; k += 64) mrow[k] = 1.0f;
        } else {
            // Batch all u loads up front (10 LDG in flight per thread)
            float uu[10];
#pragma unroll
            for (int i = 0; i < 10; i++) {
                const int k = tid + 64 * i;
                if (k < QT) uu[i] = __ldg(urow + k);
            }

            const int pq = qrow - 1;
            const int qr = (pq * 2731) >> 16;      // exact /24 for pq<576
            const int qc = pq - 24 * qr;

            // Walker tracks patch index pk = k-1 for this thread's k.
            // tid==0: first k is 0 (CLS, dy/dx forced to 0) -> start walker
            // at VIRTUAL pk=-1 == (r=0, cc=-1) so the +64 advance lands on
            // pk=63 for k=64.  (This was the round-5 bug: starting at pk=0
            // made thread 0's k=64.. elements use pk=64.. instead of 63..)
            int r, cc;
            if (tid == 0) { r = 0; cc = -1; }
            else {
                const int pk0 = tid - 1;           // in [0, 62]
                r  = (pk0 * 2731) >> 16;
                cc = pk0 - 24 * r;
            }
            float fdy = (float)(qr - r);
            float fdx = (float)(qc - cc);

#pragma unroll
            for (int i = 0; i < 10; i++) {
                const int k = tid + 64 * i;
                if (k >= QT) break;

                float dy = fdy, dx = fdx;
                if (k == 0) { dy = 0.0f; dx = 0.0f; }     // CLS key column

                float quad = a00 * dy * dy;
                quad = fmaf(a01x2 * dy, dx, quad);
                quad = fmaf(a11 * dx, dx, quad);
                quad = fmaxf(quad, 0.0f);                 // replicate min(p,1)
                const float t2 = -0.72134752044448170f * quad; // -log2(e)/2
                const float p  = exp2f(t2);

                float m;
                if (isT1) {
                    const float a  = p * uu[i];
                    const float bb = (1.0f - p) * (1.0f - uu[i]);
                    m = __fdividef(a, a + bb);
                } else {
                    const float x2 = t2 + __log2f(uu[i])
                                   - __log2f((1.0f - p) * (1.0f - uu[i]));
                    m = __fdividef(1.0f, 1.0f + exp2f(-x2 * invT));
                }
                mrow[k] = m;

                // advance patch index by 64: +2 rows, +16 cols (wrap once)
                cc += 16; fdy -= 2.0f; fdx -= 16.0f;
                if (cc >= 24) { cc -= 24; fdy -= 1.0f; fdx += 24.0f; }
            }
        }
        // No trailing sync needed: next iteration's sync #1/#2 order all
        // SMEM reuse (coefs consumed from registers).
    }
}

// ---------------------------------------------------------------------------
extern "C" void kernel_launch(void* const* d_in, const int* in_sizes, int n_in,
                              void* d_out, int out_size)
{
    const float* query = (const float*)d_in[0];
    const float* W1    = (const float*)d_in[1];
    const float* b1    = (const float*)d_in[2];
    const float* W2    = (const float*)d_in[3];
    const float* b2    = (const float*)d_in[4];
    // d_in[5] = dists (computed analytically in-kernel)
    const float* u     = (const float*)d_in[6];
    const float* temp  = (const float*)d_in[7];

    float* mask = (float*)d_out;

    float* sigma;
    if (out_size >= MASK_ELEMS + SIGMA_ELEMS) {
        sigma = (float*)d_out + MASK_ELEMS;
    } else {
        cudaGetSymbolAddress((void**)&sigma, g_sigma_fallback);
    }

    mgk_fused<<<NTOK / RPB, 64>>>(query, W1, b1, W2, b2, u, temp, mask, sigma);
}

// round 7
// speedup vs baseline: 1.2767x; 1.1889x over previous
#include <cuda_runtime.h>
#include <cuda_bf16.h>

#define QT     577
#define NTOK   55392                  // 96 * 577 rows; = 6924 * 8 exactly
#define MASK_ELEMS (96 * 577 * 577)
#define SIGMA_ELEMS (NTOK * 4)

// Fallback Sigma target if out buffer doesn't include Sigma
__device__ float g_sigma_fallback[SIGMA_ELEMS];

// ---------------------------------------------------------------------------
// Warp-autonomous fused kernel: ONE WARP = ONE ROW (token).
//  - W1 staged transposed in SMEM once per block (stride 68: 16B-aligned
//    LDS.128, each quarter-warp phase covers all 32 banks -> conflict-free).
//  - Each lane computes 2 hidden units (j=lane, lane+32): 128 FMA + GELU.
//  - Butterfly-reduce layer-2 partials; ALL lanes compute the scalar tail
//    redundantly -> no serial section, no block syncs after W1 staging.
//  - Mask: 577 elements per row, lane-coalesced k = lane + 32*i, u loads
//    batched 10-deep, dists analytic via incremental (r,cc) walker.
// max_k kernel == 1 exactly (PD form, zero CLS/self distance) => no row
// reduction. T==1 fast path: mask = p*u / (p*u + (1-p)(1-u)), p=exp(-quad/2).
// ---------------------------------------------------------------------------
__global__ __launch_bounds__(256)
void mgk_fused(const float* __restrict__ q,
               const float* __restrict__ W1, const float* __restrict__ b1,
               const float* __restrict__ W2, const float* __restrict__ b2,
               const float* __restrict__ u,  const float* __restrict__ temp,
               float* __restrict__ mask, float* __restrict__ sigma)
{
    __shared__ float w1t[64 * 68];   // W1 transposed: w1t[j*68 + k] = W1[k][j]
    __shared__ float qs[8][68];      // per-warp q row staging (float4-aligned)

    const int tid  = threadIdx.x;
    const int wid  = tid >> 5;       // warp = row within block
    const int lane = tid & 31;

    // ---- stage W1 transposed (once per block). 16 scalars per thread;
    //      gmem reads coalesced, STS conflict-free ((j+k)%32 distinct/warp).
    for (int i = tid; i < 4096; i += 256) {
        const int k = i >> 6, j = i & 63;
        w1t[j * 68 + k] = W1[i];
    }

    const int j0 = lane, j1 = lane + 32;
    const float bb0 = b1[j0], bb1 = b1[j1];
    const float w2a0 = W2[j0 * 3 + 0], w2b0 = W2[j0 * 3 + 1], w2c0 = W2[j0 * 3 + 2];
    const float w2a1 = W2[j1 * 3 + 0], w2b1 = W2[j1 * 3 + 1], w2c1 = W2[j1 * 3 + 2];
    const float b20 = b2[0], b21 = b2[1], b22 = b2[2];
    const float T    = temp[0];
    const bool  isT1 = (T == 1.0f);
    const float invT = 1.0f / T;

    const int tok = blockIdx.x * 8 + wid;      // grid*8 == NTOK exactly

    // ---- stage this warp's q row (64 floats, 256B coalesced) ----
    qs[wid][lane]      = q[(size_t)tok * 64 + lane];
    qs[wid][lane + 32] = q[(size_t)tok * 64 + 32 + lane];
    __syncthreads();                            // orders w1t + qs (only sync)

    // ---- layer 1: 2 hidden units per lane, 2 accums each ----
    float a0 = bb0, a1 = bb1, a2 = 0.0f, a3 = 0.0f;
#pragma unroll
    for (int kk = 0; kk < 16; kk += 2) {
        const float4 qv0 = *(const float4*)&qs[wid][4 * kk];
        const float4 qv1 = *(const float4*)&qs[wid][4 * kk + 4];
        const float4 wa0 = *(const float4*)&w1t[j0 * 68 + 4 * kk];
        const float4 wa1 = *(const float4*)&w1t[j0 * 68 + 4 * kk + 4];
        const float4 wb0 = *(const float4*)&w1t[j1 * 68 + 4 * kk];
        const float4 wb1 = *(const float4*)&w1t[j1 * 68 + 4 * kk + 4];
        a0 = fmaf(qv0.x, wa0.x, a0); a0 = fmaf(qv0.y, wa0.y, a0);
        a0 = fmaf(qv0.z, wa0.z, a0); a0 = fmaf(qv0.w, wa0.w, a0);
        a2 = fmaf(qv1.x, wa1.x, a2); a2 = fmaf(qv1.y, wa1.y, a2);
        a2 = fmaf(qv1.z, wa1.z, a2); a2 = fmaf(qv1.w, wa1.w, a2);
        a1 = fmaf(qv0.x, wb0.x, a1); a1 = fmaf(qv0.y, wb0.y, a1);
        a1 = fmaf(qv0.z, wb0.z, a1); a1 = fmaf(qv0.w, wb0.w, a1);
        a3 = fmaf(qv1.x, wb1.x, a3); a3 = fmaf(qv1.y, wb1.y, a3);
        a3 = fmaf(qv1.z, wb1.z, a3); a3 = fmaf(qv1.w, wb1.w, a3);
    }
    const float h0 = a0 + a2;
    const float h1 = a1 + a3;

    // Exact GELU (erf-based, matches approximate=False)
    const float g0 = 0.5f * h0 * (1.0f + erff(h0 * 0.70710678118654752f));
    const float g1 = 0.5f * h1 * (1.0f + erff(h1 * 0.70710678118654752f));

    // ---- layer 2 partials (both units) + butterfly reduce ----
    float p0 = fmaf(g1, w2a1, g0 * w2a0);
    float p1 = fmaf(g1, w2b1, g0 * w2b0);
    float p2 = fmaf(g1, w2c1, g0 * w2c0);
#pragma unroll
    for (int off = 16; off > 0; off >>= 1) {
        p0 += __shfl_xor_sync(0xffffffffu, p0, off);
        p1 += __shfl_xor_sync(0xffffffffu, p1, off);
        p2 += __shfl_xor_sync(0xffffffffu, p2, off);
    }

    // ---- scalar tail, computed redundantly by ALL lanes (no serialization)
    const float s0 = p0 + b20, s1 = p1 + b21, s2 = p2 + b22;
    const float sy  = expf(s0) + 1.0f;
    const float sx  = expf(s1) + 1.0f;
    const float rho = tanhf(s2) * 0.99f;
    const float cov = sy * sx * rho;
    if (lane == 0)
        ((float4*)sigma)[tok] = make_float4(sy * sy, cov, cov, sx * sx);

    const float om    = 1.0f - rho * rho;
    const float a00   = 1.0f / (sy * sy * om);
    const float a01x2 = -2.0f * rho / (sy * sx * om);
    const float a11   = 1.0f / (sx * sx * om);

    // ---- mask row ----
    const int    qidx = tok % QT;
    const float* urow = u    + (size_t)tok * QT;
    float*       mrow = mask + (size_t)tok * QT;

    if (qidx == 0) {
        // CLS query row: probs=1 -> logits=+inf -> mask=1 for ANY T.
        for (int k = lane; k < QT; k += 32) mrow[k] = 1.0f;
        return;
    }

    const int pq = qidx - 1;
    const int qr = (pq * 2731) >> 16;       // exact /24 for pq<576
    const int qc = pq - 24 * qr;

    // Walker over patch index pk = k-1, stepped by +32 per iteration.
    // lane 0 starts at VIRTUAL pk=-1 (k=0 is CLS, dy/dx forced 0), so the
    // +32 advance lands exactly on pk=31 for k=32.
    int r, cc;
    if (lane == 0) { r = 0; cc = -1; }
    else {
        const int pk = lane - 1;            // in [0, 30]
        r  = (pk * 2731) >> 16;
        cc = pk - 24 * r;
    }
    float fdy = (float)(qr - r);
    float fdx = (float)(qc - cc);

    // 19 strided iterations (k = lane + 32*it), u loads batched 10-deep.
#pragma unroll
    for (int c0 = 0; c0 < 19; c0 += 10) {
        float uu[10];
#pragma unroll
        for (int i2 = 0; i2 < 10; i2++) {
            const int it = c0 + i2;
            const int k  = lane + 32 * it;
            if (it < 19 && k < QT) uu[i2] = __ldg(urow + k);
        }
#pragma unroll
        for (int i2 = 0; i2 < 10; i2++) {
            const int it = c0 + i2;
            const int k  = lane + 32 * it;
            if (it < 19 && k < QT) {
                float dy = fdy, dx = fdx;
                if (k == 0) { dy = 0.0f; dx = 0.0f; }     // CLS key column

                float quad = a00 * dy * dy;
                quad = fmaf(a01x2 * dy, dx, quad);
                quad = fmaf(a11 * dx, dx, quad);
                quad = fmaxf(quad, 0.0f);                 // replicate min(p,1)
                const float t2 = -0.72134752044448170f * quad; // -log2(e)/2
                const float p  = exp2f(t2);

                float m;
                if (isT1) {
                    const float a  = p * uu[i2];
                    const float bb = (1.0f - p) * (1.0f - uu[i2]);
                    m = __fdividef(a, a + bb);
                } else {
                    const float x2 = t2 + __log2f(uu[i2])
                                   - __log2f((1.0f - p) * (1.0f - uu[i2]));
                    m = __fdividef(1.0f, 1.0f + exp2f(-x2 * invT));
                }
                mrow[k] = m;

                // advance pk by 32: +1 row, +8 cols (wrap once max)
                cc += 8; fdy -= 1.0f; fdx -= 8.0f;
                if (cc >= 24) { cc -= 24; fdy -= 1.0f; fdx += 24.0f; }
            }
        }
    }
}

// ---------------------------------------------------------------------------
extern "C" void kernel_launch(void* const* d_in, const int* in_sizes, int n_in,
                              void* d_out, int out_size)
{
    const float* query = (const float*)d_in[0];
    const float* W1    = (const float*)d_in[1];
    const float* b1    = (const float*)d_in[2];
    const float* W2    = (const float*)d_in[3];
    const float* b2    = (const float*)d_in[4];
    // d_in[5] = dists (computed analytically in-kernel)
    const float* u     = (const float*)d_in[6];
    const float* temp  = (const float*)d_in[7];

    float* mask = (float*)d_out;

    float* sigma;
    if (out_size >= MASK_ELEMS + SIGMA_ELEMS) {
        sigma = (float*)d_out + MASK_ELEMS;
    } else {
        cudaGetSymbolAddress((void**)&sigma, g_sigma_fallback);
    }

    mgk_fused<<<NTOK / 8, 256>>>(query, W1, b1, W2, b2, u, temp, mask, sigma);
}

// round 8
// speedup vs baseline: 1.4670x; 1.1491x over previous
#include <cuda_runtime.h>
#include <cuda_bf16.h>

#define QT     577
#define NTOK   55392                  // 96 * 577 rows; = 1731 * 32 exactly
#define MASK_ELEMS (96 * 577 * 577)
#define SIGMA_ELEMS (NTOK * 4)

// Fallback Sigma target if out buffer doesn't include Sigma
__device__ float g_sigma_fallback[SIGMA_ELEMS];

// ---------------------------------------------------------------------------
// Fused kernel: ONE WARP = FOUR ROWS (tokens). 256-thr block = 32 rows.
//  - W1 transposed in SMEM (stride 68: 16B-aligned LDS.128, quarter-warp
//    phases cover all 32 banks -> conflict-free).
//  - Key change vs r7: each w-float4 LDS is REUSED across 4 rows' accums,
//    cutting per-row SMEM traffic ~3x (q reads are same-address broadcasts).
//  - Per row: GELU + butterfly reduce + redundant scalar tail (no serial
//    section), then the row's 577 mask elements: lane-coalesced k=lane+32*it,
//    u loads batched 10-deep, dists analytic via incremental (r,cc) walker.
// max_k kernel == 1 exactly (PD form, zero CLS/self distance) => no row
// reduction. T==1 fast path: mask = p*u / (p*u + (1-p)(1-u)), p=exp(-quad/2).
// ---------------------------------------------------------------------------
__global__ __launch_bounds__(256)
void mgk_fused(const float* __restrict__ q,
               const float* __restrict__ W1, const float* __restrict__ b1,
               const float* __restrict__ W2, const float* __restrict__ b2,
               const float* __restrict__ u,  const float* __restrict__ temp,
               float* __restrict__ mask, float* __restrict__ sigma)
{
    __shared__ float w1t[64 * 68];    // W1 transposed: w1t[j*68+k] = W1[k][j]
    __shared__ float qs[8][4][68];    // per-warp 4 q rows (float4-aligned)

    const int tid  = threadIdx.x;
    const int wid  = tid >> 5;        // warp id: owns rows tok0..tok0+3
    const int lane = tid & 31;

    // ---- stage W1 transposed (once per block) ----
    for (int i = tid; i < 4096; i += 256) {
        const int k = i >> 6, j = i & 63;
        w1t[j * 68 + k] = W1[i];
    }

    const int j0 = lane, j1 = lane + 32;
    const float bb0 = b1[j0], bb1 = b1[j1];
    const float w2a0 = W2[j0 * 3 + 0], w2b0 = W2[j0 * 3 + 1], w2c0 = W2[j0 * 3 + 2];
    const float w2a1 = W2[j1 * 3 + 0], w2b1 = W2[j1 * 3 + 1], w2c1 = W2[j1 * 3 + 2];
    const float b20 = b2[0], b21 = b2[1], b22 = b2[2];
    const float T    = temp[0];
    const bool  isT1 = (T == 1.0f);
    const float invT = 1.0f / T;

    const int tok0 = blockIdx.x * 32 + wid * 4;

    // ---- stage the warp's 4 q rows (coalesced scalar loads) ----
#pragma unroll
    for (int r = 0; r < 4; r++) {
        qs[wid][r][lane]      = q[(size_t)(tok0 + r) * 64 + lane];
        qs[wid][r][lane + 32] = q[(size_t)(tok0 + r) * 64 + 32 + lane];
    }
    __syncthreads();                  // orders w1t (block) + qs

    // ---- layer 1: 4 rows x 2 units; w-loads amortized over rows ----
    float a00r = bb0, a01r = bb0, a02r = bb0, a03r = bb0;   // unit j0, rows 0-3
    float a10r = bb1, a11r = bb1, a12r = bb1, a13r = bb1;   // unit j1, rows 0-3
#pragma unroll
    for (int kk = 0; kk < 16; kk++) {
        const float4 wa = *(const float4*)&w1t[j0 * 68 + 4 * kk];
        const float4 wb = *(const float4*)&w1t[j1 * 68 + 4 * kk];
        const float4 q0 = *(const float4*)&qs[wid][0][4 * kk];
        const float4 q1 = *(const float4*)&qs[wid][1][4 * kk];
        const float4 q2 = *(const float4*)&qs[wid][2][4 * kk];
        const float4 q3 = *(const float4*)&qs[wid][3][4 * kk];
        a00r = fmaf(q0.x, wa.x, a00r); a00r = fmaf(q0.y, wa.y, a00r);
        a00r = fmaf(q0.z, wa.z, a00r); a00r = fmaf(q0.w, wa.w, a00r);
        a01r = fmaf(q1.x, wa.x, a01r); a01r = fmaf(q1.y, wa.y, a01r);
        a01r = fmaf(q1.z, wa.z, a01r); a01r = fmaf(q1.w, wa.w, a01r);
        a02r = fmaf(q2.x, wa.x, a02r); a02r = fmaf(q2.y, wa.y, a02r);
        a02r = fmaf(q2.z, wa.z, a02r); a02r = fmaf(q2.w, wa.w, a02r);
        a03r = fmaf(q3.x, wa.x, a03r); a03r = fmaf(q3.y, wa.y, a03r);
        a03r = fmaf(q3.z, wa.z, a03r); a03r = fmaf(q3.w, wa.w, a03r);
        a10r = fmaf(q0.x, wb.x, a10r); a10r = fmaf(q0.y, wb.y, a10r);
        a10r = fmaf(q0.z, wb.z, a10r); a10r = fmaf(q0.w, wb.w, a10r);
        a11r = fmaf(q1.x, wb.x, a11r); a11r = fmaf(q1.y, wb.y, a11r);
        a11r = fmaf(q1.z, wb.z, a11r); a11r = fmaf(q1.w, wb.w, a11r);
        a12r = fmaf(q2.x, wb.x, a12r); a12r = fmaf(q2.y, wb.y, a12r);
        a12r = fmaf(q2.z, wb.z, a12r); a12r = fmaf(q2.w, wb.w, a12r);
        a13r = fmaf(q3.x, wb.x, a13r); a13r = fmaf(q3.y, wb.y, a13r);
        a13r = fmaf(q3.z, wb.z, a13r); a13r = fmaf(q3.w, wb.w, a13r);
    }

    // ---- per-row: GELU, reduce, tail, mask stream (loop kept rolled) ----
    for (int r4 = 0; r4 < 4; r4++) {
        const int tok = tok0 + r4;

        const float h0 = (r4 == 0) ? a00r : (r4 == 1) ? a01r
                        : (r4 == 2) ? a02r : a03r;
        const float h1 = (r4 == 0) ? a10r : (r4 == 1) ? a11r
                        : (r4 == 2) ? a12r : a13r;

        // Exact GELU (erf-based, matches approximate=False)
        const float g0 = 0.5f * h0 * (1.0f + erff(h0 * 0.70710678118654752f));
        const float g1 = 0.5f * h1 * (1.0f + erff(h1 * 0.70710678118654752f));

        float p0 = fmaf(g1, w2a1, g0 * w2a0);
        float p1 = fmaf(g1, w2b1, g0 * w2b0);
        float p2 = fmaf(g1, w2c1, g0 * w2c0);
#pragma unroll
        for (int off = 16; off > 0; off >>= 1) {
            p0 += __shfl_xor_sync(0xffffffffu, p0, off);
            p1 += __shfl_xor_sync(0xffffffffu, p1, off);
            p2 += __shfl_xor_sync(0xffffffffu, p2, off);
        }

        // scalar tail, redundantly on all lanes (no serialization)
        const float s0 = p0 + b20, s1 = p1 + b21, s2 = p2 + b22;
        const float sy  = expf(s0) + 1.0f;
        const float sx  = expf(s1) + 1.0f;
        const float rho = tanhf(s2) * 0.99f;
        const float cov = sy * sx * rho;
        if (lane == 0)
            ((float4*)sigma)[tok] = make_float4(sy * sy, cov, cov, sx * sx);

        const float om    = 1.0f - rho * rho;
        const float c00   = 1.0f / (sy * sy * om);
        const float c01x2 = -2.0f * rho / (sy * sx * om);
        const float c11   = 1.0f / (sx * sx * om);

        const int    qidx = tok % QT;
        const float* urow = u    + (size_t)tok * QT;
        float*       mrow = mask + (size_t)tok * QT;

        if (qidx == 0) {
            // CLS query row: probs=1 -> logits=+inf -> mask=1 for ANY T.
            for (int k = lane; k < QT; k += 32) mrow[k] = 1.0f;
            continue;
        }

        const int pq = qidx - 1;
        const int qr = (pq * 2731) >> 16;       // exact /24 for pq<576
        const int qc = pq - 24 * qr;

        // Walker over patch index pk = k-1, stepped +32 per iteration.
        // lane 0 starts at VIRTUAL pk=-1 (k=0 is CLS, dy/dx forced 0) so the
        // +32 advance lands exactly on pk=31 for k=32.
        int r, cc;
        if (lane == 0) { r = 0; cc = -1; }
        else {
            const int pk = lane - 1;            // in [0, 30]
            r  = (pk * 2731) >> 16;
            cc = pk - 24 * r;
        }
        float fdy = (float)(qr - r);
        float fdx = (float)(qc - cc);

        // 19 strided iterations (k = lane + 32*it), u loads batched 10-deep
#pragma unroll
        for (int c0 = 0; c0 < 19; c0 += 10) {
            float uu[10];
#pragma unroll
            for (int i2 = 0; i2 < 10; i2++) {
                const int it = c0 + i2;
                const int k  = lane + 32 * it;
                if (it < 19 && k < QT) uu[i2] = __ldg(urow + k);
            }
#pragma unroll
            for (int i2 = 0; i2 < 10; i2++) {
                const int it = c0 + i2;
                const int k  = lane + 32 * it;
                if (it < 19 && k < QT) {
                    float dy = fdy, dx = fdx;
                    if (k == 0) { dy = 0.0f; dx = 0.0f; }   // CLS key column

                    float quad = c00 * dy * dy;
                    quad = fmaf(c01x2 * dy, dx, quad);
                    quad = fmaf(c11 * dx, dx, quad);
                    quad = fmaxf(quad, 0.0f);               // min(probs,1)
                    const float t2 = -0.72134752044448170f * quad;
                    const float p  = exp2f(t2);

                    float m;
                    if (isT1) {
                        const float a  = p * uu[i2];
                        const float bb = (1.0f - p) * (1.0f - uu[i2]);
                        m = __fdividef(a, a + bb);
                    } else {
                        const float x2 = t2 + __log2f(uu[i2])
                                       - __log2f((1.0f - p) * (1.0f - uu[i2]));
                        m = __fdividef(1.0f, 1.0f + exp2f(-x2 * invT));
                    }
                    mrow[k] = m;

                    // advance pk by 32: +1 row, +8 cols (wrap once max)
                    cc += 8; fdy -= 1.0f; fdx -= 8.0f;
                    if (cc >= 24) { cc -= 24; fdy -= 1.0f; fdx += 24.0f; }
                }
            }
        }
    }
}

// ---------------------------------------------------------------------------
extern "C" void kernel_launch(void* const* d_in, const int* in_sizes, int n_in,
                              void* d_out, int out_size)
{
    const float* query = (const float*)d_in[0];
    const float* W1    = (const float*)d_in[1];
    const float* b1    = (const float*)d_in[2];
    const float* W2    = (const float*)d_in[3];
    const float* b2    = (const float*)d_in[4];
    // d_in[5] = dists (computed analytically in-kernel)
    const float* u     = (const float*)d_in[6];
    const float* temp  = (const float*)d_in[7];

    float* mask = (float*)d_out;

    float* sigma;
    if (out_size >= MASK_ELEMS + SIGMA_ELEMS) {
        sigma = (float*)d_out + MASK_ELEMS;
    } else {
        cudaGetSymbolAddress((void**)&sigma, g_sigma_fallback);
    }

    mgk_fused<<<NTOK / 32, 256>>>(query, W1, b1, W2, b2, u, temp, mask, sigma);
}

// round 9
// speedup vs baseline: 1.5798x; 1.0769x over previous
#include <cuda_runtime.h>
#include <cuda_bf16.h>

#define QT     577
#define NTOK   55392                  // 96 * 577 rows; = 1731 * 32 exactly
#define MASK_ELEMS (96 * 577 * 577)
#define SIGMA_ELEMS (NTOK * 4)

// Fallback Sigma target if out buffer doesn't include Sigma
__device__ float g_sigma_fallback[SIGMA_ELEMS];

// ---------------------------------------------------------------------------
// Fused kernel: ONE WARP = FOUR ROWS. 256-thr block = 32 rows, 4 blocks/SM.
//  - MLP: W1 transposed in SMEM (stride 68), each w-float4 LDS reused across
//    the warp's 4 rows. Butterfly reduce; scalar tail redundant on all lanes.
//  - Mask: float2-vectorized. Row base parity off = tok&1 keeps the global
//    element index EVEN at pair starts -> aligned LDG.64/STG.64. 9 predicate-
//    free iterations cover 576 elements; the leftover singleton is either
//    k=0 (CLS column => mask==1 exactly) or k=576 (one scalar compute).
//  - dists analytic: walker over patch idx pk=k-1 advanced once per PAIR
//    (+64 => +2 rows +16 cols, one wrap max); pair's 2nd element derived
//    with a single cc==23 select.
// max_k kernel == 1 exactly (PD form, zero CLS/self distance) => no row
// reduction. T==1 fast path: mask = p*u / (p*u + (1-p)(1-u)), p=exp(-quad/2).
// ---------------------------------------------------------------------------
__global__ __launch_bounds__(256, 4)
void mgk_fused(const float* __restrict__ q,
               const float* __restrict__ W1, const float* __restrict__ b1,
               const float* __restrict__ W2, const float* __restrict__ b2,
               const float* __restrict__ u,  const float* __restrict__ temp,
               float* __restrict__ mask, float* __restrict__ sigma)
{
    __shared__ float w1t[64 * 68];    // W1 transposed: w1t[j*68+k] = W1[k][j]
    __shared__ float qs[8][4][68];    // per-warp 4 q rows (float4-aligned)

    const int tid  = threadIdx.x;
    const int wid  = tid >> 5;
    const int lane = tid & 31;

    // ---- stage W1 transposed (once per block) ----
    for (int i = tid; i < 4096; i += 256) {
        const int k = i >> 6, j = i & 63;
        w1t[j * 68 + k] = W1[i];
    }

    const int j0 = lane, j1 = lane + 32;
    const float bb0 = b1[j0], bb1 = b1[j1];
    const float w2a0 = W2[j0 * 3 + 0], w2b0 = W2[j0 * 3 + 1], w2c0 = W2[j0 * 3 + 2];
    const float w2a1 = W2[j1 * 3 + 0], w2b1 = W2[j1 * 3 + 1], w2c1 = W2[j1 * 3 + 2];
    const float b20 = b2[0], b21 = b2[1], b22 = b2[2];
    const float T    = temp[0];
    const bool  isT1 = (T == 1.0f);
    const float invT = 1.0f / T;

    const int tok0 = blockIdx.x * 32 + wid * 4;

    // ---- stage the warp's 4 q rows ----
#pragma unroll
    for (int r = 0; r < 4; r++) {
        qs[wid][r][lane]      = q[(size_t)(tok0 + r) * 64 + lane];
        qs[wid][r][lane + 32] = q[(size_t)(tok0 + r) * 64 + 32 + lane];
    }
    __syncthreads();

    // ---- layer 1: 4 rows x 2 units; w-loads amortized across rows ----
    float a00r = bb0, a01r = bb0, a02r = bb0, a03r = bb0;
    float a10r = bb1, a11r = bb1, a12r = bb1, a13r = bb1;
#pragma unroll
    for (int kk = 0; kk < 16; kk++) {
        const float4 wa = *(const float4*)&w1t[j0 * 68 + 4 * kk];
        const float4 wb = *(const float4*)&w1t[j1 * 68 + 4 * kk];
        const float4 q0 = *(const float4*)&qs[wid][0][4 * kk];
        const float4 q1 = *(const float4*)&qs[wid][1][4 * kk];
        const float4 q2 = *(const float4*)&qs[wid][2][4 * kk];
        const float4 q3 = *(const float4*)&qs[wid][3][4 * kk];
        a00r = fmaf(q0.x, wa.x, a00r); a00r = fmaf(q0.y, wa.y, a00r);
        a00r = fmaf(q0.z, wa.z, a00r); a00r = fmaf(q0.w, wa.w, a00r);
        a01r = fmaf(q1.x, wa.x, a01r); a01r = fmaf(q1.y, wa.y, a01r);
        a01r = fmaf(q1.z, wa.z, a01r); a01r = fmaf(q1.w, wa.w, a01r);
        a02r = fmaf(q2.x, wa.x, a02r); a02r = fmaf(q2.y, wa.y, a02r);
        a02r = fmaf(q2.z, wa.z, a02r); a02r = fmaf(q2.w, wa.w, a02r);
        a03r = fmaf(q3.x, wa.x, a03r); a03r = fmaf(q3.y, wa.y, a03r);
        a03r = fmaf(q3.z, wa.z, a03r); a03r = fmaf(q3.w, wa.w, a03r);
        a10r = fmaf(q0.x, wb.x, a10r); a10r = fmaf(q0.y, wb.y, a10r);
        a10r = fmaf(q0.z, wb.z, a10r); a10r = fmaf(q0.w, wb.w, a10r);
        a11r = fmaf(q1.x, wb.x, a11r); a11r = fmaf(q1.y, wb.y, a11r);
        a11r = fmaf(q1.z, wb.z, a11r); a11r = fmaf(q1.w, wb.w, a11r);
        a12r = fmaf(q2.x, wb.x, a12r); a12r = fmaf(q2.y, wb.y, a12r);
        a12r = fmaf(q2.z, wb.z, a12r); a12r = fmaf(q2.w, wb.w, a12r);
        a13r = fmaf(q3.x, wb.x, a13r); a13r = fmaf(q3.y, wb.y, a13r);
        a13r = fmaf(q3.z, wb.z, a13r); a13r = fmaf(q3.w, wb.w, a13r);
    }

    // ---- per-row: GELU, reduce, tail, vectorized mask stream ----
#pragma unroll 1
    for (int r4 = 0; r4 < 4; r4++) {
        const int tok = tok0 + r4;

        const float h0 = (r4 == 0) ? a00r : (r4 == 1) ? a01r
                        : (r4 == 2) ? a02r : a03r;
        const float h1 = (r4 == 0) ? a10r : (r4 == 1) ? a11r
                        : (r4 == 2) ? a12r : a13r;

        // Exact GELU (erf-based, matches approximate=False)
        const float g0 = 0.5f * h0 * (1.0f + erff(h0 * 0.70710678118654752f));
        const float g1 = 0.5f * h1 * (1.0f + erff(h1 * 0.70710678118654752f));

        float p0 = fmaf(g1, w2a1, g0 * w2a0);
        float p1 = fmaf(g1, w2b1, g0 * w2b0);
        float p2 = fmaf(g1, w2c1, g0 * w2c0);
#pragma unroll
        for (int off = 16; off > 0; off >>= 1) {
            p0 += __shfl_xor_sync(0xffffffffu, p0, off);
            p1 += __shfl_xor_sync(0xffffffffu, p1, off);
            p2 += __shfl_xor_sync(0xffffffffu, p2, off);
        }

        const float s0 = p0 + b20, s1 = p1 + b21, s2 = p2 + b22;
        const float sy  = expf(s0) + 1.0f;
        const float sx  = expf(s1) + 1.0f;
        const float rho = tanhf(s2) * 0.99f;
        const float cov = sy * sx * rho;
        if (lane == 0)
            ((float4*)sigma)[tok] = make_float4(sy * sy, cov, cov, sx * sx);

        const float om    = 1.0f - rho * rho;
        const float c00   = 1.0f / (sy * sy * om);
        const float c01x2 = -2.0f * rho / (sy * sx * om);
        const float c11   = 1.0f / (sx * sx * om);

        const int    qidx = tok % QT;
        const float* urow = u    + (size_t)tok * QT;
        float*       mrow = mask + (size_t)tok * QT;

        if (qidx == 0) {
            // CLS query row: probs=1 -> mask=1 for ANY T.
            for (int k = lane; k < QT; k += 32) mrow[k] = 1.0f;
            continue;
        }

        const int pq = qidx - 1;
        const int qr = (pq * 2731) >> 16;       // exact /24 for pq<576
        const int qc = pq - 24 * qr;

        const int off = tok & 1;                // row-base parity (577 odd)
        // aligned float2 views starting at element k=off (global idx even)
        const float2* up = (const float2*)(urow + off);
        float2*       mp = (float2*)(mrow + off);

        if (off == 1 && lane == 0)
            mrow[0] = 1.0f;                     // CLS key column: mask==1

        // Walker at the pair's FIRST element: pk0 = off + 2*lane - 1.
        // off==0, lane==0 -> virtual pk=-1 (k=0 is CLS, dy/dx overridden).
        int r, cc;
        {
            const int pk0 = off + 2 * lane - 1;
            if (pk0 < 0) { r = 0; cc = -1; }
            else { r = (pk0 * 2731) >> 16; cc = pk0 - 24 * r; }
        }
        float fdy = (float)(qr - r);
        float fdx = (float)(qc - cc);
        const bool iscls = (off == 0) && (lane == 0);

        // 9 predicate-free iterations, u loads batched 5 + 4
#pragma unroll
        for (int c0 = 0; c0 < 9; c0 += 5) {
            const int nb = (c0 == 0) ? 5 : 4;
            float2 uu[5];
#pragma unroll
            for (int i2 = 0; i2 < 5; i2++)
                if (i2 < nb) uu[i2] = __ldg(up + lane + 32 * (c0 + i2));
#pragma unroll
            for (int i2 = 0; i2 < 5; i2++) {
                if (i2 >= nb) continue;
                const int it = c0 + i2;

                float dy1 = fdy, dx1 = fdx;
                if (it == 0 && iscls) { dy1 = 0.0f; dx1 = 0.0f; }
                const bool wrap = (cc == 23);
                const float dy2 = wrap ? fdy - 1.0f  : fdy;
                const float dx2 = wrap ? fdx + 23.0f : fdx - 1.0f;

                float qd1 = c00 * dy1 * dy1;
                qd1 = fmaf(c01x2 * dy1, dx1, qd1);
                qd1 = fmaf(c11 * dx1, dx1, qd1);
                qd1 = fmaxf(qd1, 0.0f);
                float qd2 = c00 * dy2 * dy2;
                qd2 = fmaf(c01x2 * dy2, dx2, qd2);
                qd2 = fmaf(c11 * dx2, dx2, qd2);
                qd2 = fmaxf(qd2, 0.0f);

                const float t21 = -0.72134752044448170f * qd1;
                const float t22 = -0.72134752044448170f * qd2;
                const float pe1 = exp2f(t21);
                const float pe2 = exp2f(t22);
                const float u1 = uu[i2].x, u2 = uu[i2].y;

                float m1, m2;
                if (isT1) {
                    const float n1 = pe1 * u1, d1 = (1.0f - pe1) * (1.0f - u1);
                    const float n2 = pe2 * u2, d2 = (1.0f - pe2) * (1.0f - u2);
                    m1 = __fdividef(n1, n1 + d1);
                    m2 = __fdividef(n2, n2 + d2);
                } else {
                    const float x1 = t21 + __log2f(u1)
                                   - __log2f((1.0f - pe1) * (1.0f - u1));
                    const float x2 = t22 + __log2f(u2)
                                   - __log2f((1.0f - pe2) * (1.0f - u2));
                    m1 = __fdividef(1.0f, 1.0f + exp2f(-x1 * invT));
                    m2 = __fdividef(1.0f, 1.0f + exp2f(-x2 * invT));
                }
                mp[lane + 32 * it] = make_float2(m1, m2);

                // advance pair start by 64 keys: +2 rows, +16 cols (<=1 wrap)
                cc += 16; fdy -= 2.0f; fdx -= 16.0f;
                if (cc >= 24) { cc -= 24; fdy -= 1.0f; fdx += 24.0f; }
            }
        }

        if (off == 0 && lane == 0) {
            // tail singleton k=576 -> pk=575 -> (r,cc)=(23,23)
            const float dy = (float)(qr - 23);
            const float dx = (float)(qc - 23);
            float qd = c00 * dy * dy;
            qd = fmaf(c01x2 * dy, dx, qd);
            qd = fmaf(c11 * dx, dx, qd);
            qd = fmaxf(qd, 0.0f);
            const float t2 = -0.72134752044448170f * qd;
            const float pe = exp2f(t2);
            const float uu = __ldg(urow + 576);
            float m;
            if (isT1) {
                const float n = pe * uu, d = (1.0f - pe) * (1.0f - uu);
                m = __fdividef(n, n + d);
            } else {
                const float x2 = t2 + __log2f(uu)
                               - __log2f((1.0f - pe) * (1.0f - uu));
                m = __fdividef(1.0f, 1.0f + exp2f(-x2 * invT));
            }
            mrow[576] = m;
        }
    }
}

// ---------------------------------------------------------------------------
extern "C" void kernel_launch(void* const* d_in, const int* in_sizes, int n_in,
                              void* d_out, int out_size)
{
    const float* query = (const float*)d_in[0];
    const float* W1    = (const float*)d_in[1];
    const float* b1    = (const float*)d_in[2];
    const float* W2    = (const float*)d_in[3];
    const float* b2    = (const float*)d_in[4];
    // d_in[5] = dists (computed analytically in-kernel)
    const float* u     = (const float*)d_in[6];
    const float* temp  = (const float*)d_in[7];

    float* mask = (float*)d_out;

    float* sigma;
    if (out_size >= MASK_ELEMS + SIGMA_ELEMS) {
        sigma = (float*)d_out + MASK_ELEMS;
    } else {
        cudaGetSymbolAddress((void**)&sigma, g_sigma_fallback);
    }

    mgk_fused<<<NTOK / 32, 256>>>(query, W1, b1, W2, b2, u, temp, mask, sigma);
}